// round 14
// baseline (speedup 1.0000x reference)
#include <cuda_runtime.h>
#include <cuda_fp16.h>
#include <cstdint>
#include <cstddef>

#define TT 8192
#define EE 4096

// ---------------- scratch (device globals) ----------------------------------
__device__ __half g_X[(size_t)EE * EE];      // X = att * Wv^T [E,E]
__device__ __half g_wtH[(size_t)EE * EE];    // Wq^T hi
__device__ __half g_wtL[(size_t)EE * EE];
__device__ __half g_wkH[(size_t)EE * EE];    // Wk^T hi
__device__ __half g_wkL[(size_t)EE * EE];
__device__ __half g_wvH[(size_t)EE * EE];    // Wv as half (row-major)
__device__ __half g_wpH[(size_t)TT * TT];    // Wp^T hi
__device__ __half g_ttH[(size_t)EE * TT];    // tokens^T [E,T] (read-only after prep)
__device__ __half g_ttL[(size_t)EE * TT];
__device__ __half g_A2H[(size_t)EE * EE];    // A2 = Wq^T G hi
__device__ __half g_A2L[(size_t)EE * EE];    // A2 lo
__device__ __half g_GH[(size_t)EE * EE];     // G hi
__device__ __half g_GL[(size_t)EE * EE];     // G lo
__device__ __half g_PT[(size_t)TT * EE];     // PT [T,E]
__device__ float  g_S[(size_t)EE * EE];      // logits fp32
__device__ __half g_attH[(size_t)EE * EE];   // att fp16
__device__ float  g_part[32 * TT];           // colsum partials (side stream only)
__device__ float  g_u[EE];                   // colsum(tokens)
__device__ float  g_alpha[EE];               // Wq^T u
__device__ float  g_betat[EE];               // Wk^T u + T*bk
__device__ float  g_avb[EE];                 // att * bv
__device__ float  g_wpc[TT];                 // colsum(Wp)

// ---------------- helpers ---------------------------------------------------
__device__ __forceinline__ uint32_t s2u(const void* p) {
    uint32_t a;
    asm("{ .reg .u64 t; cvta.to.shared.u64 t, %1; cvt.u32.u64 %0, t; }"
        : "=r"(a) : "l"(p));
    return a;
}
__device__ __forceinline__ void cp16(uint32_t dst, const void* src) {
    asm volatile("cp.async.cg.shared.global [%0], [%1], 16;"
                 :: "r"(dst), "l"(src));
}
#define CP_COMMIT() asm volatile("cp.async.commit_group;" ::: "memory")
#define CP_WAIT1()  asm volatile("cp.async.wait_group 1;" ::: "memory")
#define CP_WAIT2()  asm volatile("cp.async.wait_group 2;" ::: "memory")

#define LDSM4(r, a)                                                          \
    asm volatile("ldmatrix.sync.aligned.m8n8.x4.shared.b16 "                 \
                 "{%0,%1,%2,%3}, [%4];"                                      \
                 : "=r"((r)[0]), "=r"((r)[1]), "=r"((r)[2]), "=r"((r)[3])    \
                 : "r"(a))

#define MMA16816(c, a, b0, b1)                                               \
    asm volatile("mma.sync.aligned.m16n8k16.row.col.f32.f16.f16.f32 "        \
                 "{%0,%1,%2,%3}, {%4,%5,%6,%7}, {%8,%9}, {%0,%1,%2,%3};"     \
                 : "+f"((c)[0]), "+f"((c)[1]), "+f"((c)[2]), "+f"((c)[3])    \
                 : "r"((a)[0]), "r"((a)[1]), "r"((a)[2]), "r"((a)[3]),       \
                   "r"(b0), "r"(b1))

__device__ __forceinline__ __half hhi(float v) { return __float2half(v); }
__device__ __forceinline__ __half hlo(float v, __half h) {
    return __float2half(v - __half2float(h));
}

// ================= split fp16 HMMA GEMM (hh+hl+lh) ==========================
#define BM 128
#define BN 256
#define BKT 32
#define PITCH 80
#define A_HL 10240
#define B_OFF 20480
#define B_HL 20480
#define STAGE 61440
#define NST 3

// OUTM: 0 = fp32 out, 1 = split half out.
// SYM: 1 = C symmetric (skip strictly-lower blocks; mirror-write transpose).
template <int OUTM, int SYM>
__global__ __launch_bounds__(256, 1)
void gemm_mma(const __half* __restrict__ Ah, const __half* __restrict__ Al,
              const __half* __restrict__ Bh, const __half* __restrict__ Bl,
              void* __restrict__ Co, void* __restrict__ Col,
              int M, int N, int K)
{
    extern __shared__ char dsm[];
    const uint32_t sb = s2u(dsm);

    const int tid  = threadIdx.x;
    const int wid  = tid >> 5;
    const int lane = tid & 31;
    const int bm = blockIdx.y * BM;
    const int bn = blockIdx.x * BN;
    if (SYM && bm >= bn + BN) return;
    const int m0 = (wid >> 2) * 64;
    const int n0 = (wid & 3) * 64;
    const int kt = K / BKT;

    auto load_stage = [&](int slot, int tile) {
        const uint32_t base = sb + slot * STAGE;
        const int k0 = tile * BKT;
        #pragma unroll
        for (int j = 0; j < 12; j++) {
            int c = tid + j * 256;
            uint32_t dst;
            const __half* src;
            if (c < 1024) {
                int hl = c >> 9, row = (c >> 2) & 127, ch = c & 3;
                dst = base + hl * A_HL + row * PITCH + ch * 16;
                const __half* p = hl ? Al : Ah;
                src = p + (size_t)(bm + row) * K + k0 + ch * 8;
            } else {
                int cc = c - 1024;
                int hl = cc >> 10, row = (cc >> 2) & 255, ch = cc & 3;
                dst = base + B_OFF + hl * B_HL + row * PITCH + ch * 16;
                const __half* p = hl ? Bl : Bh;
                src = p + (size_t)(bn + row) * K + k0 + ch * 8;
            }
            cp16(dst, src);
        }
    };

    float acc[4][8][4];
    #pragma unroll
    for (int mt = 0; mt < 4; mt++)
        #pragma unroll
        for (int nt = 0; nt < 8; nt++)
            #pragma unroll
            for (int r = 0; r < 4; r++) acc[mt][nt][r] = 0.f;

    const uint32_t rowA = (uint32_t)(m0 + (lane & 15)) * PITCH + ((lane >> 4) << 4);
    const int quad = lane >> 3, rl = lane & 7;
    const uint32_t rowB = (uint32_t)(n0 + ((quad >> 1) << 3) + rl) * PITCH
                        + ((quad & 1) << 4);

    load_stage(0, 0); CP_COMMIT();
    if (kt > 1) load_stage(1, 1);
    CP_COMMIT();

    for (int i = 0; i < kt; i++) {
        CP_WAIT1();
        __syncthreads();
        const int nxt = i + NST - 1;
        if (nxt < kt) load_stage(nxt % NST, nxt);
        CP_COMMIT();

        const uint32_t base = sb + (i % NST) * STAGE;
        #pragma unroll
        for (int ks = 0; ks < 2; ks++) {
            const uint32_t ko = ks * 32;
            uint32_t ah[4][4], bh[4][4], al[4][4], bl[4][4];
            #pragma unroll
            for (int mt = 0; mt < 4; mt++)
                LDSM4(ah[mt], base + rowA + mt * (16 * PITCH) + ko);
            #pragma unroll
            for (int np = 0; np < 4; np++)
                LDSM4(bh[np], base + B_OFF + rowB + np * (16 * PITCH) + ko);
            #pragma unroll
            for (int mt = 0; mt < 4; mt++)
                LDSM4(al[mt], base + A_HL + rowA + mt * (16 * PITCH) + ko);
            #pragma unroll
            for (int np = 0; np < 4; np++)
                LDSM4(bl[np], base + B_OFF + B_HL + rowB + np * (16 * PITCH) + ko);
            #pragma unroll
            for (int mt = 0; mt < 4; mt++)
                #pragma unroll
                for (int nt = 0; nt < 8; nt++)
                    MMA16816(acc[mt][nt], ah[mt], bh[nt >> 1][(nt & 1) * 2],
                             bh[nt >> 1][(nt & 1) * 2 + 1]);
            #pragma unroll
            for (int mt = 0; mt < 4; mt++)
                #pragma unroll
                for (int nt = 0; nt < 8; nt++)
                    MMA16816(acc[mt][nt], ah[mt], bl[nt >> 1][(nt & 1) * 2],
                             bl[nt >> 1][(nt & 1) * 2 + 1]);
            #pragma unroll
            for (int mt = 0; mt < 4; mt++)
                #pragma unroll
                for (int nt = 0; nt < 8; nt++)
                    MMA16816(acc[mt][nt], al[mt], bh[nt >> 1][(nt & 1) * 2],
                             bh[nt >> 1][(nt & 1) * 2 + 1]);
        }
    }

    const int r1 = lane >> 2;
    const int cb = (lane & 3) * 2;
    #pragma unroll
    for (int nt = 0; nt < 8; nt++) {
        const int col = bn + n0 + nt * 8 + cb;
        #pragma unroll
        for (int mt = 0; mt < 4; mt++) {
            const int row = bm + m0 + mt * 16 + r1;
            float v0 = acc[mt][nt][0];
            float v1 = acc[mt][nt][1];
            float v2 = acc[mt][nt][2];
            float v3 = acc[mt][nt][3];
            if (OUTM == 0) {
                float* C = (float*)Co;
                *reinterpret_cast<float2*>(C + (size_t)row * N + col) =
                    make_float2(v0, v1);
                *reinterpret_cast<float2*>(C + (size_t)(row + 8) * N + col) =
                    make_float2(v2, v3);
            } else {
                __half* H = (__half*)Co;
                __half* L = (__half*)Col;
                __half2 h01, l01, h23, l23;
                h01.x = hhi(v0); h01.y = hhi(v1);
                l01.x = hlo(v0, h01.x); l01.y = hlo(v1, h01.y);
                h23.x = hhi(v2); h23.y = hhi(v3);
                l23.x = hlo(v2, h23.x); l23.y = hlo(v3, h23.y);
                *reinterpret_cast<__half2*>(H + (size_t)row * N + col) = h01;
                *reinterpret_cast<__half2*>(L + (size_t)row * N + col) = l01;
                *reinterpret_cast<__half2*>(H + (size_t)(row + 8) * N + col) = h23;
                *reinterpret_cast<__half2*>(L + (size_t)(row + 8) * N + col) = l23;
                if (SYM) {
                    H[(size_t)col * N + row]           = h01.x;
                    H[(size_t)(col + 1) * N + row]     = h01.y;
                    L[(size_t)col * N + row]           = l01.x;
                    L[(size_t)(col + 1) * N + row]     = l01.y;
                    H[(size_t)col * N + row + 8]       = h23.x;
                    H[(size_t)(col + 1) * N + row + 8] = h23.y;
                    L[(size_t)col * N + row + 8]       = l23.x;
                    L[(size_t)(col + 1) * N + row + 8] = l23.y;
                }
            }
        }
    }
}

// ================= single-pass fp16 HMMA GEMM ================================
#define SBKT 64
#define S_AOFF 0
#define S_BOFF 16384
#define S_STAGE 49152
#define S_NST 4

// OUTM: 0 = fp32 out, 2 = single half out.
// BIASM: 0 none, 1 per-col bias[n], 3 = bias[n] + rbias[m]*cwp[n] (rank-1).
template <int OUTM, int BIASM>
__global__ __launch_bounds__(512, 1)
void gemm_s(const __half* __restrict__ Ah, const __half* __restrict__ Bh,
            void* __restrict__ Co, const float* __restrict__ bias,
            const float* __restrict__ rbias, const float* __restrict__ cwp,
            int M, int N, int K)
{
    extern __shared__ char dsm[];
    const uint32_t sb = s2u(dsm);

    const int tid  = threadIdx.x;
    const int wid  = tid >> 5;
    const int lane = tid & 31;
    const int bm = blockIdx.y * BM;
    const int bn = blockIdx.x * BN;
    const int m0 = (wid >> 2) * 32;
    const int n0 = (wid & 3) * 64;
    const int kt = K / SBKT;

    auto load_stage = [&](int slot, int tile) {
        const uint32_t base = sb + slot * S_STAGE;
        const int k0 = tile * SBKT;
        #pragma unroll
        for (int j = 0; j < 6; j++) {
            int c = tid + j * 512;
            uint32_t dst;
            const __half* src;
            if (c < 1024) {
                int row = c >> 3, ch = c & 7;
                dst = base + S_AOFF + row * 128 + ((ch ^ (row & 7)) << 4);
                src = Ah + (size_t)(bm + row) * K + k0 + ch * 8;
            } else {
                int cc = c - 1024;
                int row = cc >> 3, ch = cc & 7;
                dst = base + S_BOFF + row * 128 + ((ch ^ (row & 7)) << 4);
                src = Bh + (size_t)(bn + row) * K + k0 + ch * 8;
            }
            cp16(dst, src);
        }
    };

    float acc[2][8][4];
    #pragma unroll
    for (int mt = 0; mt < 2; mt++)
        #pragma unroll
        for (int nt = 0; nt < 8; nt++)
            #pragma unroll
            for (int r = 0; r < 4; r++) acc[mt][nt][r] = 0.f;

    int rA[2], rB[4];
    #pragma unroll
    for (int mt = 0; mt < 2; mt++) rA[mt] = m0 + mt * 16 + (lane & 15);
    const int quad = lane >> 3, rl = lane & 7;
    #pragma unroll
    for (int np = 0; np < 4; np++) rB[np] = n0 + np * 16 + ((quad >> 1) << 3) + rl;
    const int cA = lane >> 4;
    const int cB = quad & 1;

    load_stage(0, 0); CP_COMMIT();
    load_stage(1, 1); CP_COMMIT();
    load_stage(2, 2); CP_COMMIT();

    for (int i = 0; i < kt; i++) {
        CP_WAIT2();
        __syncthreads();
        const int nxt = i + S_NST - 1;
        if (nxt < kt) load_stage(nxt & (S_NST - 1), nxt);
        CP_COMMIT();

        const uint32_t base = sb + (i & (S_NST - 1)) * S_STAGE;
        #pragma unroll
        for (int ks = 0; ks < 4; ks++) {
            uint32_t ah[2][4], bh[4][4];
            #pragma unroll
            for (int mt = 0; mt < 2; mt++) {
                int ch = (cA + 2 * ks) ^ (rA[mt] & 7);
                LDSM4(ah[mt], base + S_AOFF + rA[mt] * 128 + (ch << 4));
            }
            #pragma unroll
            for (int np = 0; np < 4; np++) {
                int ch = (cB + 2 * ks) ^ (rB[np] & 7);
                LDSM4(bh[np], base + S_BOFF + rB[np] * 128 + (ch << 4));
            }
            #pragma unroll
            for (int mt = 0; mt < 2; mt++)
                #pragma unroll
                for (int nt = 0; nt < 8; nt++)
                    MMA16816(acc[mt][nt], ah[mt], bh[nt >> 1][(nt & 1) * 2],
                             bh[nt >> 1][(nt & 1) * 2 + 1]);
        }
    }

    const int r1 = lane >> 2;
    const int cb = (lane & 3) * 2;
    float rbA[2], rbB[2];
    #pragma unroll
    for (int mt = 0; mt < 2; mt++) {
        if (BIASM == 3) {
            rbA[mt] = rbias[bm + m0 + mt * 16 + r1];
            rbB[mt] = rbias[bm + m0 + mt * 16 + r1 + 8];
        } else { rbA[mt] = 0.f; rbB[mt] = 0.f; }
    }
    #pragma unroll
    for (int nt = 0; nt < 8; nt++) {
        const int col = bn + n0 + nt * 8 + cb;
        float cb0 = 0.f, cb1 = 0.f, w0 = 0.f, w1 = 0.f;
        if (BIASM >= 1) { cb0 = bias[col]; cb1 = bias[col + 1]; }
        if (BIASM == 3) { w0 = cwp[col]; w1 = cwp[col + 1]; }
        #pragma unroll
        for (int mt = 0; mt < 2; mt++) {
            const int row = bm + m0 + mt * 16 + r1;
            float v0 = acc[mt][nt][0] + cb0 + rbA[mt] * w0;
            float v1 = acc[mt][nt][1] + cb1 + rbA[mt] * w1;
            float v2 = acc[mt][nt][2] + cb0 + rbB[mt] * w0;
            float v3 = acc[mt][nt][3] + cb1 + rbB[mt] * w1;
            if (OUTM == 0) {
                float* C = (float*)Co;
                *reinterpret_cast<float2*>(C + (size_t)row * N + col) =
                    make_float2(v0, v1);
                *reinterpret_cast<float2*>(C + (size_t)(row + 8) * N + col) =
                    make_float2(v2, v3);
            } else {
                __half* H = (__half*)Co;
                __half2 h01, h23;
                h01.x = hhi(v0); h01.y = hhi(v1);
                h23.x = hhi(v2); h23.y = hhi(v3);
                *reinterpret_cast<__half2*>(H + (size_t)row * N + col) = h01;
                *reinterpret_cast<__half2*>(H + (size_t)(row + 8) * N + col) = h23;
            }
        }
    }
}

// ---------------- split / transpose preps ----------------------------------
__global__ void split_kernel(const float* __restrict__ in,
                             __half* __restrict__ oh,
                             __half* __restrict__ ol, size_t n4)
{
    size_t i = (size_t)blockIdx.x * 256 + threadIdx.x;
    if (i >= n4) return;
    float4 v = reinterpret_cast<const float4*>(in)[i];
    __half h0 = hhi(v.x), h1 = hhi(v.y), h2 = hhi(v.z), h3 = hhi(v.w);
    __half2 H0; H0.x = h0; H0.y = h1;
    __half2 H1; H1.x = h2; H1.y = h3;
    reinterpret_cast<__half2*>(oh)[2 * i]     = H0;
    reinterpret_cast<__half2*>(oh)[2 * i + 1] = H1;
    if (ol != nullptr) {
        __half2 L0; L0.x = hlo(v.x, h0); L0.y = hlo(v.y, h1);
        __half2 L1; L1.x = hlo(v.z, h2); L1.y = hlo(v.w, h3);
        reinterpret_cast<__half2*>(ol)[2 * i]     = L0;
        reinterpret_cast<__half2*>(ol)[2 * i + 1] = L1;
    }
}

// in [R,C] fp32 -> oh/ol [C,R] half; ol may be null
__global__ void splitT_kernel(const float* __restrict__ in,
                              __half* __restrict__ oh,
                              __half* __restrict__ ol, int R, int C)
{
    __shared__ float t[32][33];
    int x  = blockIdx.x * 32 + threadIdx.x;
    int y0 = blockIdx.y * 32;
    #pragma unroll
    for (int j = 0; j < 32; j += 8)
        t[threadIdx.y + j][threadIdx.x] = in[(size_t)(y0 + threadIdx.y + j) * C + x];
    __syncthreads();
    int ox  = y0 + threadIdx.x;
    int oy0 = blockIdx.x * 32;
    #pragma unroll
    for (int j = 0; j < 32; j += 8) {
        float v = t[threadIdx.x][threadIdx.y + j];
        __half h = hhi(v);
        size_t idx = (size_t)(oy0 + threadIdx.y + j) * R + ox;
        oh[idx] = h;
        if (ol != nullptr) ol[idx] = hlo(v, h);
    }
}

// ---------------- colsum (rows = gridDim.y*256, width W) ---------------------
__global__ void colsum_partial(const float* __restrict__ in,
                               float* __restrict__ part, int W)
{
    int e = blockIdx.x * 256 + threadIdx.x;
    int y = blockIdx.y;
    float s = 0.f;
    const float* p = in + (size_t)y * 256 * W + e;
    #pragma unroll 8
    for (int t = 0; t < 256; t++) s += p[(size_t)t * W];
    part[(size_t)y * W + e] = s;
}
__global__ void colsum_final(const float* __restrict__ part,
                             float* __restrict__ u, int W, int ny)
{
    int e = blockIdx.x * 256 + threadIdx.x;
    float s = 0.f;
    for (int y = 0; y < ny; y++) s += part[(size_t)y * W + e];
    u[e] = s;
}
// out[i] = sum_a W[a,i]*u[a] + scale*badd[i]   (W is EE x EE)
__global__ void matvecT(const float* __restrict__ W, const float* __restrict__ u,
                        const float* __restrict__ badd, float scale,
                        float* __restrict__ out)
{
    int i = blockIdx.x * 256 + threadIdx.x;
    float s = 0.f;
    for (int a = 0; a < EE; a++) s += W[(size_t)a * EE + i] * u[a];
    out[i] = s + scale * badd[i];
}

// ------- softmax (+rank-1 logit correction) -> fp16 att, + avb = att*bv ------
__global__ void softmax_half(const float* __restrict__ S,
                             __half* __restrict__ oh, int n,
                             const float* __restrict__ bq,
                             const float* __restrict__ bk,
                             const float* __restrict__ alpha,
                             const float* __restrict__ betat,
                             const float* __restrict__ bv,
                             float* __restrict__ avb)
{
    const int tid = threadIdx.x;
    const int row = blockIdx.x;
    const float* p = S + (size_t)row * n;
    const float bqr = bq[row];
    const float alr = alpha[row];
    float v[16];
    float m = -3.4e38f;
    #pragma unroll
    for (int i = 0; i < 16; i++) {
        int j = tid + (i << 8);
        v[i] = p[j] + bqr * betat[j] + alr * bk[j];
        m = fmaxf(m, v[i]);
    }
    __shared__ float red[8];
    #pragma unroll
    for (int o = 16; o > 0; o >>= 1)
        m = fmaxf(m, __shfl_xor_sync(0xffffffffu, m, o));
    if ((tid & 31) == 0) red[tid >> 5] = m;
    __syncthreads();
    float M = red[0];
    #pragma unroll
    for (int i = 1; i < 8; i++) M = fmaxf(M, red[i]);

    float s = 0.f;
    #pragma unroll
    for (int i = 0; i < 16; i++) {
        v[i] = expf(v[i] - M);
        s += v[i];
    }
    __syncthreads();
    #pragma unroll
    for (int o = 16; o > 0; o >>= 1)
        s += __shfl_xor_sync(0xffffffffu, s, o);
    if ((tid & 31) == 0) red[tid >> 5] = s;
    __syncthreads();
    float tot = 0.f;
    #pragma unroll
    for (int i = 0; i < 8; i++) tot += red[i];
    const float inv = 1.0f / tot;

    __half* ph = oh + (size_t)row * n;
    float d = 0.f;
    #pragma unroll
    for (int i = 0; i < 16; i++) {
        int j = tid + (i << 8);
        float w = v[i] * inv;
        ph[j] = hhi(w);
        d += w * bv[j];
    }
    __syncthreads();
    #pragma unroll
    for (int o = 16; o > 0; o >>= 1)
        d += __shfl_xor_sync(0xffffffffu, d, o);
    if ((tid & 31) == 0) red[tid >> 5] = d;
    __syncthreads();
    if (tid == 0) {
        float td = 0.f;
        #pragma unroll
        for (int i = 0; i < 8; i++) td += red[i];
        avb[row] = td;
    }
}

// ---------------- host ------------------------------------------------------
extern "C" void kernel_launch(void* const* d_in, const int* in_sizes, int n_in,
                              void* d_out, int out_size)
{
    (void)in_sizes; (void)n_in; (void)out_size;
    const float* tokens = (const float*)d_in[0];
    const float* Wq = (const float*)d_in[1];
    const float* bq = (const float*)d_in[2];
    const float* Wk = (const float*)d_in[3];
    const float* bk = (const float*)d_in[4];
    const float* Wv = (const float*)d_in[5];
    const float* bv = (const float*)d_in[6];
    const float* Wp = (const float*)d_in[7];
    const float* bp = (const float*)d_in[8];
    float* out = (float*)d_out;

    __half *X, *wtH, *wtL, *wkH, *wkL, *wvH, *wpH, *ttH, *ttL;
    __half *A2H, *A2L, *GH, *GL, *PT, *attH;
    float *S, *part, *u, *alpha, *betat, *avb, *wpc;
    cudaGetSymbolAddress((void**)&X, g_X);
    cudaGetSymbolAddress((void**)&wtH, g_wtH);
    cudaGetSymbolAddress((void**)&wtL, g_wtL);
    cudaGetSymbolAddress((void**)&wkH, g_wkH);
    cudaGetSymbolAddress((void**)&wkL, g_wkL);
    cudaGetSymbolAddress((void**)&wvH, g_wvH);
    cudaGetSymbolAddress((void**)&wpH, g_wpH);
    cudaGetSymbolAddress((void**)&ttH, g_ttH);
    cudaGetSymbolAddress((void**)&ttL, g_ttL);
    cudaGetSymbolAddress((void**)&A2H, g_A2H);
    cudaGetSymbolAddress((void**)&A2L, g_A2L);
    cudaGetSymbolAddress((void**)&GH, g_GH);
    cudaGetSymbolAddress((void**)&GL, g_GL);
    cudaGetSymbolAddress((void**)&PT, g_PT);
    cudaGetSymbolAddress((void**)&attH, g_attH);
    cudaGetSymbolAddress((void**)&S, g_S);
    cudaGetSymbolAddress((void**)&part, g_part);
    cudaGetSymbolAddress((void**)&u, g_u);
    cudaGetSymbolAddress((void**)&alpha, g_alpha);
    cudaGetSymbolAddress((void**)&betat, g_betat);
    cudaGetSymbolAddress((void**)&avb, g_avb);
    cudaGetSymbolAddress((void**)&wpc, g_wpc);

    const int T = TT, E = EE;
    const int QM = E / 4;                     // row-quarter of the post-G chain

    static bool init_done = false;
    static cudaStream_t sB = nullptr;
    static cudaEvent_t eF = nullptr, eT = nullptr, eP = nullptr;
    static cudaEvent_t eJ = nullptr, eG = nullptr, eEnd = nullptr;
    if (!init_done) {
        cudaFuncSetAttribute(gemm_mma<1, 1>, cudaFuncAttributeMaxDynamicSharedMemorySize, NST * STAGE);
        cudaFuncSetAttribute(gemm_mma<1, 0>, cudaFuncAttributeMaxDynamicSharedMemorySize, NST * STAGE);
        cudaFuncSetAttribute(gemm_mma<0, 0>, cudaFuncAttributeMaxDynamicSharedMemorySize, NST * STAGE);
        cudaFuncSetAttribute(gemm_s<2, 0>, cudaFuncAttributeMaxDynamicSharedMemorySize, S_NST * S_STAGE);
        cudaFuncSetAttribute(gemm_s<0, 3>, cudaFuncAttributeMaxDynamicSharedMemorySize, S_NST * S_STAGE);
        cudaStreamCreateWithFlags(&sB, cudaStreamNonBlocking);
        cudaEventCreateWithFlags(&eF, cudaEventDisableTiming);
        cudaEventCreateWithFlags(&eT, cudaEventDisableTiming);
        cudaEventCreateWithFlags(&eP, cudaEventDisableTiming);
        cudaEventCreateWithFlags(&eJ, cudaEventDisableTiming);
        cudaEventCreateWithFlags(&eG, cudaEventDisableTiming);
        cudaEventCreateWithFlags(&eEnd, cudaEventDisableTiming);
        init_done = true;
    }
    const size_t smem  = NST * STAGE;
    const size_t smemS = S_NST * S_STAGE;
    dim3 blkT(32, 8);

    // fork side stream at the very start
    cudaEventRecord(eF, 0);
    cudaStreamWaitEvent(sB, eF, 0);

    // --- stream 0: tokens^T (split) -> G -> quarters 0,2 ---
    splitT_kernel<<<dim3(E / 32, T / 32), blkT>>>(tokens, ttH, ttL, T, E);
    cudaEventRecord(eT, 0);

    // --- side stream: all W-preps + colsums + matvecs, then Wp^T + PT ---
    splitT_kernel<<<dim3(E / 32, E / 32), blkT, 0, sB>>>(Wq, wtH, wtL, E, E);
    splitT_kernel<<<dim3(E / 32, E / 32), blkT, 0, sB>>>(Wk, wkH, wkL, E, E);
    split_kernel<<<(unsigned)((size_t)E * E / 4 / 256), 256, 0, sB>>>(
        Wv, wvH, nullptr, (size_t)E * E / 4);
    colsum_partial<<<dim3(E / 256, 32), 256, 0, sB>>>(tokens, part, E);
    colsum_final<<<E / 256, 256, 0, sB>>>(part, u, E, 32);
    matvecT<<<E / 256, 256, 0, sB>>>(Wq, u, bq, 0.f, alpha);
    matvecT<<<E / 256, 256, 0, sB>>>(Wk, u, bk, (float)T, betat);
    colsum_partial<<<dim3(T / 256, 32), 256, 0, sB>>>(Wp, part, T);
    colsum_final<<<T / 256, 256, 0, sB>>>(part, wpc, T, 32);
    cudaEventRecord(eP, sB);            // small preps done
    splitT_kernel<<<dim3(T / 32, T / 32), blkT, 0, sB>>>(Wp, wpH, nullptr, T, T);
    cudaStreamWaitEvent(sB, eT, 0);     // PT needs tokens^T
    gemm_s<2, 0><<<dim3(E / BN, T / BM), 512, smemS, sB>>>(
        wpH, ttH, PT, nullptr, nullptr, nullptr, T, E, T);
    cudaEventRecord(eJ, sB);            // PT ready

    // G = tok^T tok [E,E], symmetric, split out  (stream 0)
    gemm_mma<1, 1><<<dim3(E / BN, E / BM), 256, smem>>>(
        ttH, ttL, ttH, ttL, GH, GL, E, E, T);
    cudaEventRecord(eG, 0);

    cudaStreamWaitEvent(0, eP, 0);      // stream-0 quarters need W-preps
    cudaStreamWaitEvent(sB, eG, 0);     // side-stream quarters need G

    // quarter pipeline launcher: q = 0..3, stream st
    auto quarter = [&](int q, cudaStream_t st, bool needPT) {
        const size_t oE = (size_t)q * QM * E;     // offset in [E,E] mats
        const size_t oT = (size_t)q * QM * T;     // offset in out [E,T]
        const int    oV = q * QM;                 // offset in row-vectors
        gemm_mma<1, 0><<<dim3(E / BN, QM / BM), 256, smem, st>>>(
            wtH + oE, wtL + oE, GH, GL, A2H + oE, A2L + oE, QM, E, E);
        gemm_mma<0, 0><<<dim3(E / BN, QM / BM), 256, smem, st>>>(
            A2H + oE, A2L + oE, wkH, wkL, S + oE, nullptr, QM, E, E);
        softmax_half<<<QM, 256, 0, st>>>(S + oE, attH + oE, E,
                                         bq + oV, bk, alpha + oV, betat, bv, avb + oV);
        gemm_s<2, 0><<<dim3(E / BN, QM / BM), 512, smemS, st>>>(
            attH + oE, wvH, X + oE, nullptr, nullptr, nullptr, QM, E, E);
        if (needPT) cudaStreamWaitEvent(st, eJ, 0);   // final needs PT (once/stream)
        gemm_s<0, 3><<<dim3(T / BN, QM / BM), 512, smemS, st>>>(
            X + oE, PT, out + oT, bp, avb + oV, wpc, QM, T, E);
    };

    quarter(0, 0, true);            // stream 0: quarters 0, 2
    quarter(1, sB, false);          // side stream after PT: order guarantees PT done
    quarter(2, 0, false);
    quarter(3, sB, false);

    cudaEventRecord(eEnd, sB);
    cudaStreamWaitEvent(0, eEnd, 0);   // harness syncs stream 0
}

// round 15
// speedup vs baseline: 1.0155x; 1.0155x over previous
#include <cuda_runtime.h>
#include <cuda_fp16.h>
#include <cstdint>
#include <cstddef>

#define TT 8192
#define EE 4096

// ---------------- scratch (device globals) ----------------------------------
__device__ __half g_X[(size_t)EE * EE];      // X = att * Wv^T [E,E]
__device__ __half g_wtH[(size_t)EE * EE];    // Wq^T hi
__device__ __half g_wtL[(size_t)EE * EE];
__device__ __half g_wkH[(size_t)EE * EE];    // Wk^T hi
__device__ __half g_wkL[(size_t)EE * EE];
__device__ __half g_wvH[(size_t)EE * EE];    // Wv as half (row-major)
__device__ __half g_wpH[(size_t)TT * TT];    // Wp^T hi
__device__ __half g_ttH[(size_t)EE * TT];    // tokens^T [E,T] (read-only after prep)
__device__ __half g_ttL[(size_t)EE * TT];
__device__ __half g_A2H[(size_t)EE * EE];    // A2 = Wq^T G hi
__device__ __half g_A2L[(size_t)EE * EE];    // A2 lo
__device__ __half g_GH[(size_t)EE * EE];     // G hi
__device__ __half g_GL[(size_t)EE * EE];     // G lo
__device__ __half g_PT[(size_t)TT * EE];     // PT [T,E]
__device__ float  g_S[(size_t)EE * EE];      // logits fp32
__device__ __half g_attH[(size_t)EE * EE];   // att fp16
__device__ float  g_part[32 * TT];           // colsum partials (side stream only)
__device__ float  g_u[EE];                   // colsum(tokens)
__device__ float  g_alpha[EE];               // Wq^T u
__device__ float  g_betat[EE];               // Wk^T u + T*bk
__device__ float  g_avb[EE];                 // att * bv
__device__ float  g_wpc[TT];                 // colsum(Wp)

// ---------------- helpers ---------------------------------------------------
__device__ __forceinline__ uint32_t s2u(const void* p) {
    uint32_t a;
    asm("{ .reg .u64 t; cvta.to.shared.u64 t, %1; cvt.u32.u64 %0, t; }"
        : "=r"(a) : "l"(p));
    return a;
}
__device__ __forceinline__ void cp16(uint32_t dst, const void* src) {
    asm volatile("cp.async.cg.shared.global [%0], [%1], 16;"
                 :: "r"(dst), "l"(src));
}
#define CP_COMMIT() asm volatile("cp.async.commit_group;" ::: "memory")
#define CP_WAIT1()  asm volatile("cp.async.wait_group 1;" ::: "memory")
#define CP_WAIT2()  asm volatile("cp.async.wait_group 2;" ::: "memory")

#define LDSM4(r, a)                                                          \
    asm volatile("ldmatrix.sync.aligned.m8n8.x4.shared.b16 "                 \
                 "{%0,%1,%2,%3}, [%4];"                                      \
                 : "=r"((r)[0]), "=r"((r)[1]), "=r"((r)[2]), "=r"((r)[3])    \
                 : "r"(a))

#define MMA16816(c, a, b0, b1)                                               \
    asm volatile("mma.sync.aligned.m16n8k16.row.col.f32.f16.f16.f32 "        \
                 "{%0,%1,%2,%3}, {%4,%5,%6,%7}, {%8,%9}, {%0,%1,%2,%3};"     \
                 : "+f"((c)[0]), "+f"((c)[1]), "+f"((c)[2]), "+f"((c)[3])    \
                 : "r"((a)[0]), "r"((a)[1]), "r"((a)[2]), "r"((a)[3]),       \
                   "r"(b0), "r"(b1))

__device__ __forceinline__ __half hhi(float v) { return __float2half(v); }
__device__ __forceinline__ __half hlo(float v, __half h) {
    return __float2half(v - __half2float(h));
}

// ================= split fp16 HMMA GEMM (hh+hl+lh) ==========================
#define BM 128
#define BN 256
#define BKT 32
#define PITCH 80
#define A_HL 10240
#define B_OFF 20480
#define B_HL 20480
#define STAGE 61440
#define NST 3

// OUTM: 0 = fp32 out, 1 = split half out.
// SYM: 1 = C symmetric (skip strictly-lower blocks; mirror-write transpose).
template <int OUTM, int SYM>
__global__ __launch_bounds__(256, 1)
void gemm_mma(const __half* __restrict__ Ah, const __half* __restrict__ Al,
              const __half* __restrict__ Bh, const __half* __restrict__ Bl,
              void* __restrict__ Co, void* __restrict__ Col,
              int M, int N, int K)
{
    extern __shared__ char dsm[];
    const uint32_t sb = s2u(dsm);

    const int tid  = threadIdx.x;
    const int wid  = tid >> 5;
    const int lane = tid & 31;
    const int bm = blockIdx.y * BM;
    const int bn = blockIdx.x * BN;
    if (SYM && bm >= bn + BN) return;
    const int m0 = (wid >> 2) * 64;
    const int n0 = (wid & 3) * 64;
    const int kt = K / BKT;

    auto load_stage = [&](int slot, int tile) {
        const uint32_t base = sb + slot * STAGE;
        const int k0 = tile * BKT;
        #pragma unroll
        for (int j = 0; j < 12; j++) {
            int c = tid + j * 256;
            uint32_t dst;
            const __half* src;
            if (c < 1024) {
                int hl = c >> 9, row = (c >> 2) & 127, ch = c & 3;
                dst = base + hl * A_HL + row * PITCH + ch * 16;
                const __half* p = hl ? Al : Ah;
                src = p + (size_t)(bm + row) * K + k0 + ch * 8;
            } else {
                int cc = c - 1024;
                int hl = cc >> 10, row = (cc >> 2) & 255, ch = cc & 3;
                dst = base + B_OFF + hl * B_HL + row * PITCH + ch * 16;
                const __half* p = hl ? Bl : Bh;
                src = p + (size_t)(bn + row) * K + k0 + ch * 8;
            }
            cp16(dst, src);
        }
    };

    float acc[4][8][4];
    #pragma unroll
    for (int mt = 0; mt < 4; mt++)
        #pragma unroll
        for (int nt = 0; nt < 8; nt++)
            #pragma unroll
            for (int r = 0; r < 4; r++) acc[mt][nt][r] = 0.f;

    const uint32_t rowA = (uint32_t)(m0 + (lane & 15)) * PITCH + ((lane >> 4) << 4);
    const int quad = lane >> 3, rl = lane & 7;
    const uint32_t rowB = (uint32_t)(n0 + ((quad >> 1) << 3) + rl) * PITCH
                        + ((quad & 1) << 4);

    load_stage(0, 0); CP_COMMIT();
    if (kt > 1) load_stage(1, 1);
    CP_COMMIT();

    for (int i = 0; i < kt; i++) {
        CP_WAIT1();
        __syncthreads();
        const int nxt = i + NST - 1;
        if (nxt < kt) load_stage(nxt % NST, nxt);
        CP_COMMIT();

        const uint32_t base = sb + (i % NST) * STAGE;
        #pragma unroll
        for (int ks = 0; ks < 2; ks++) {
            const uint32_t ko = ks * 32;
            uint32_t ah[4][4], bh[4][4], al[4][4], bl[4][4];
            #pragma unroll
            for (int mt = 0; mt < 4; mt++)
                LDSM4(ah[mt], base + rowA + mt * (16 * PITCH) + ko);
            #pragma unroll
            for (int np = 0; np < 4; np++)
                LDSM4(bh[np], base + B_OFF + rowB + np * (16 * PITCH) + ko);
            #pragma unroll
            for (int mt = 0; mt < 4; mt++)
                LDSM4(al[mt], base + A_HL + rowA + mt * (16 * PITCH) + ko);
            #pragma unroll
            for (int np = 0; np < 4; np++)
                LDSM4(bl[np], base + B_OFF + B_HL + rowB + np * (16 * PITCH) + ko);
            #pragma unroll
            for (int mt = 0; mt < 4; mt++)
                #pragma unroll
                for (int nt = 0; nt < 8; nt++)
                    MMA16816(acc[mt][nt], ah[mt], bh[nt >> 1][(nt & 1) * 2],
                             bh[nt >> 1][(nt & 1) * 2 + 1]);
            #pragma unroll
            for (int mt = 0; mt < 4; mt++)
                #pragma unroll
                for (int nt = 0; nt < 8; nt++)
                    MMA16816(acc[mt][nt], ah[mt], bl[nt >> 1][(nt & 1) * 2],
                             bl[nt >> 1][(nt & 1) * 2 + 1]);
            #pragma unroll
            for (int mt = 0; mt < 4; mt++)
                #pragma unroll
                for (int nt = 0; nt < 8; nt++)
                    MMA16816(acc[mt][nt], al[mt], bh[nt >> 1][(nt & 1) * 2],
                             bh[nt >> 1][(nt & 1) * 2 + 1]);
        }
    }

    const int r1 = lane >> 2;
    const int cb = (lane & 3) * 2;
    #pragma unroll
    for (int nt = 0; nt < 8; nt++) {
        const int col = bn + n0 + nt * 8 + cb;
        #pragma unroll
        for (int mt = 0; mt < 4; mt++) {
            const int row = bm + m0 + mt * 16 + r1;
            float v0 = acc[mt][nt][0];
            float v1 = acc[mt][nt][1];
            float v2 = acc[mt][nt][2];
            float v3 = acc[mt][nt][3];
            if (OUTM == 0) {
                float* C = (float*)Co;
                *reinterpret_cast<float2*>(C + (size_t)row * N + col) =
                    make_float2(v0, v1);
                *reinterpret_cast<float2*>(C + (size_t)(row + 8) * N + col) =
                    make_float2(v2, v3);
            } else {
                __half* H = (__half*)Co;
                __half* L = (__half*)Col;
                __half2 h01, l01, h23, l23;
                h01.x = hhi(v0); h01.y = hhi(v1);
                l01.x = hlo(v0, h01.x); l01.y = hlo(v1, h01.y);
                h23.x = hhi(v2); h23.y = hhi(v3);
                l23.x = hlo(v2, h23.x); l23.y = hlo(v3, h23.y);
                *reinterpret_cast<__half2*>(H + (size_t)row * N + col) = h01;
                *reinterpret_cast<__half2*>(L + (size_t)row * N + col) = l01;
                *reinterpret_cast<__half2*>(H + (size_t)(row + 8) * N + col) = h23;
                *reinterpret_cast<__half2*>(L + (size_t)(row + 8) * N + col) = l23;
                if (SYM) {
                    H[(size_t)col * N + row]           = h01.x;
                    H[(size_t)(col + 1) * N + row]     = h01.y;
                    L[(size_t)col * N + row]           = l01.x;
                    L[(size_t)(col + 1) * N + row]     = l01.y;
                    H[(size_t)col * N + row + 8]       = h23.x;
                    H[(size_t)(col + 1) * N + row + 8] = h23.y;
                    L[(size_t)col * N + row + 8]       = l23.x;
                    L[(size_t)(col + 1) * N + row + 8] = l23.y;
                }
            }
        }
    }
}

// ================= single-pass fp16 HMMA GEMM ================================
#define SBKT 64
#define S_AOFF 0
#define S_BOFF 16384
#define S_STAGE 49152
#define S_NST 4

// OUTM: 0 = fp32 out, 2 = single half out.
// BIASM: 0 none, 1 per-col bias[n], 3 = bias[n] + rbias[m]*cwp[n] (rank-1).
template <int OUTM, int BIASM>
__global__ __launch_bounds__(512, 1)
void gemm_s(const __half* __restrict__ Ah, const __half* __restrict__ Bh,
            void* __restrict__ Co, const float* __restrict__ bias,
            const float* __restrict__ rbias, const float* __restrict__ cwp,
            int M, int N, int K)
{
    extern __shared__ char dsm[];
    const uint32_t sb = s2u(dsm);

    const int tid  = threadIdx.x;
    const int wid  = tid >> 5;
    const int lane = tid & 31;
    const int bm = blockIdx.y * BM;
    const int bn = blockIdx.x * BN;
    const int m0 = (wid >> 2) * 32;
    const int n0 = (wid & 3) * 64;
    const int kt = K / SBKT;

    auto load_stage = [&](int slot, int tile) {
        const uint32_t base = sb + slot * S_STAGE;
        const int k0 = tile * SBKT;
        #pragma unroll
        for (int j = 0; j < 6; j++) {
            int c = tid + j * 512;
            uint32_t dst;
            const __half* src;
            if (c < 1024) {
                int row = c >> 3, ch = c & 7;
                dst = base + S_AOFF + row * 128 + ((ch ^ (row & 7)) << 4);
                src = Ah + (size_t)(bm + row) * K + k0 + ch * 8;
            } else {
                int cc = c - 1024;
                int row = cc >> 3, ch = cc & 7;
                dst = base + S_BOFF + row * 128 + ((ch ^ (row & 7)) << 4);
                src = Bh + (size_t)(bn + row) * K + k0 + ch * 8;
            }
            cp16(dst, src);
        }
    };

    float acc[2][8][4];
    #pragma unroll
    for (int mt = 0; mt < 2; mt++)
        #pragma unroll
        for (int nt = 0; nt < 8; nt++)
            #pragma unroll
            for (int r = 0; r < 4; r++) acc[mt][nt][r] = 0.f;

    int rA[2], rB[4];
    #pragma unroll
    for (int mt = 0; mt < 2; mt++) rA[mt] = m0 + mt * 16 + (lane & 15);
    const int quad = lane >> 3, rl = lane & 7;
    #pragma unroll
    for (int np = 0; np < 4; np++) rB[np] = n0 + np * 16 + ((quad >> 1) << 3) + rl;
    const int cA = lane >> 4;
    const int cB = quad & 1;

    load_stage(0, 0); CP_COMMIT();
    load_stage(1, 1); CP_COMMIT();
    load_stage(2, 2); CP_COMMIT();

    for (int i = 0; i < kt; i++) {
        CP_WAIT2();
        __syncthreads();
        const int nxt = i + S_NST - 1;
        if (nxt < kt) load_stage(nxt & (S_NST - 1), nxt);
        CP_COMMIT();

        const uint32_t base = sb + (i & (S_NST - 1)) * S_STAGE;
        #pragma unroll
        for (int ks = 0; ks < 4; ks++) {
            uint32_t ah[2][4], bh[4][4];
            #pragma unroll
            for (int mt = 0; mt < 2; mt++) {
                int ch = (cA + 2 * ks) ^ (rA[mt] & 7);
                LDSM4(ah[mt], base + S_AOFF + rA[mt] * 128 + (ch << 4));
            }
            #pragma unroll
            for (int np = 0; np < 4; np++) {
                int ch = (cB + 2 * ks) ^ (rB[np] & 7);
                LDSM4(bh[np], base + S_BOFF + rB[np] * 128 + (ch << 4));
            }
            #pragma unroll
            for (int mt = 0; mt < 2; mt++)
                #pragma unroll
                for (int nt = 0; nt < 8; nt++)
                    MMA16816(acc[mt][nt], ah[mt], bh[nt >> 1][(nt & 1) * 2],
                             bh[nt >> 1][(nt & 1) * 2 + 1]);
        }
    }

    const int r1 = lane >> 2;
    const int cb = (lane & 3) * 2;
    float rbA[2], rbB[2];
    #pragma unroll
    for (int mt = 0; mt < 2; mt++) {
        if (BIASM == 3) {
            rbA[mt] = rbias[bm + m0 + mt * 16 + r1];
            rbB[mt] = rbias[bm + m0 + mt * 16 + r1 + 8];
        } else { rbA[mt] = 0.f; rbB[mt] = 0.f; }
    }
    #pragma unroll
    for (int nt = 0; nt < 8; nt++) {
        const int col = bn + n0 + nt * 8 + cb;
        float cb0 = 0.f, cb1 = 0.f, w0 = 0.f, w1 = 0.f;
        if (BIASM >= 1) { cb0 = bias[col]; cb1 = bias[col + 1]; }
        if (BIASM == 3) { w0 = cwp[col]; w1 = cwp[col + 1]; }
        #pragma unroll
        for (int mt = 0; mt < 2; mt++) {
            const int row = bm + m0 + mt * 16 + r1;
            float v0 = acc[mt][nt][0] + cb0 + rbA[mt] * w0;
            float v1 = acc[mt][nt][1] + cb1 + rbA[mt] * w1;
            float v2 = acc[mt][nt][2] + cb0 + rbB[mt] * w0;
            float v3 = acc[mt][nt][3] + cb1 + rbB[mt] * w1;
            if (OUTM == 0) {
                float* C = (float*)Co;
                *reinterpret_cast<float2*>(C + (size_t)row * N + col) =
                    make_float2(v0, v1);
                *reinterpret_cast<float2*>(C + (size_t)(row + 8) * N + col) =
                    make_float2(v2, v3);
            } else {
                __half* H = (__half*)Co;
                __half2 h01, h23;
                h01.x = hhi(v0); h01.y = hhi(v1);
                h23.x = hhi(v2); h23.y = hhi(v3);
                *reinterpret_cast<__half2*>(H + (size_t)row * N + col) = h01;
                *reinterpret_cast<__half2*>(H + (size_t)(row + 8) * N + col) = h23;
            }
        }
    }
}

// ---------------- split / transpose preps ----------------------------------
__global__ void split_kernel(const float* __restrict__ in,
                             __half* __restrict__ oh,
                             __half* __restrict__ ol, size_t n4)
{
    size_t i = (size_t)blockIdx.x * 256 + threadIdx.x;
    if (i >= n4) return;
    float4 v = reinterpret_cast<const float4*>(in)[i];
    __half h0 = hhi(v.x), h1 = hhi(v.y), h2 = hhi(v.z), h3 = hhi(v.w);
    __half2 H0; H0.x = h0; H0.y = h1;
    __half2 H1; H1.x = h2; H1.y = h3;
    reinterpret_cast<__half2*>(oh)[2 * i]     = H0;
    reinterpret_cast<__half2*>(oh)[2 * i + 1] = H1;
    if (ol != nullptr) {
        __half2 L0; L0.x = hlo(v.x, h0); L0.y = hlo(v.y, h1);
        __half2 L1; L1.x = hlo(v.z, h2); L1.y = hlo(v.w, h3);
        reinterpret_cast<__half2*>(ol)[2 * i]     = L0;
        reinterpret_cast<__half2*>(ol)[2 * i + 1] = L1;
    }
}

// in [R,C] fp32 -> oh/ol [C,R] half; ol may be null
__global__ void splitT_kernel(const float* __restrict__ in,
                              __half* __restrict__ oh,
                              __half* __restrict__ ol, int R, int C)
{
    __shared__ float t[32][33];
    int x  = blockIdx.x * 32 + threadIdx.x;
    int y0 = blockIdx.y * 32;
    #pragma unroll
    for (int j = 0; j < 32; j += 8)
        t[threadIdx.y + j][threadIdx.x] = in[(size_t)(y0 + threadIdx.y + j) * C + x];
    __syncthreads();
    int ox  = y0 + threadIdx.x;
    int oy0 = blockIdx.x * 32;
    #pragma unroll
    for (int j = 0; j < 32; j += 8) {
        float v = t[threadIdx.x][threadIdx.y + j];
        __half h = hhi(v);
        size_t idx = (size_t)(oy0 + threadIdx.y + j) * R + ox;
        oh[idx] = h;
        if (ol != nullptr) ol[idx] = hlo(v, h);
    }
}

// ---------------- colsum (rows = gridDim.y*256, width W) ---------------------
__global__ void colsum_partial(const float* __restrict__ in,
                               float* __restrict__ part, int W)
{
    int e = blockIdx.x * 256 + threadIdx.x;
    int y = blockIdx.y;
    float s = 0.f;
    const float* p = in + (size_t)y * 256 * W + e;
    #pragma unroll 8
    for (int t = 0; t < 256; t++) s += p[(size_t)t * W];
    part[(size_t)y * W + e] = s;
}
__global__ void colsum_final(const float* __restrict__ part,
                             float* __restrict__ u, int W, int ny)
{
    int e = blockIdx.x * 256 + threadIdx.x;
    float s = 0.f;
    for (int y = 0; y < ny; y++) s += part[(size_t)y * W + e];
    u[e] = s;
}
// out[i] = sum_a W[a,i]*u[a] + scale*badd[i]   (W is EE x EE)
__global__ void matvecT(const float* __restrict__ W, const float* __restrict__ u,
                        const float* __restrict__ badd, float scale,
                        float* __restrict__ out)
{
    int i = blockIdx.x * 256 + threadIdx.x;
    float s = 0.f;
    for (int a = 0; a < EE; a++) s += W[(size_t)a * EE + i] * u[a];
    out[i] = s + scale * badd[i];
}

// ------- softmax (+rank-1 logit correction) -> fp16 att, + avb = att*bv ------
__global__ void softmax_half(const float* __restrict__ S,
                             __half* __restrict__ oh, int n,
                             const float* __restrict__ bq,
                             const float* __restrict__ bk,
                             const float* __restrict__ alpha,
                             const float* __restrict__ betat,
                             const float* __restrict__ bv,
                             float* __restrict__ avb)
{
    const int tid = threadIdx.x;
    const int row = blockIdx.x;
    const float* p = S + (size_t)row * n;
    const float bqr = bq[row];
    const float alr = alpha[row];
    float v[16];
    float m = -3.4e38f;
    #pragma unroll
    for (int i = 0; i < 16; i++) {
        int j = tid + (i << 8);
        v[i] = p[j] + bqr * betat[j] + alr * bk[j];
        m = fmaxf(m, v[i]);
    }
    __shared__ float red[8];
    #pragma unroll
    for (int o = 16; o > 0; o >>= 1)
        m = fmaxf(m, __shfl_xor_sync(0xffffffffu, m, o));
    if ((tid & 31) == 0) red[tid >> 5] = m;
    __syncthreads();
    float M = red[0];
    #pragma unroll
    for (int i = 1; i < 8; i++) M = fmaxf(M, red[i]);

    float s = 0.f;
    #pragma unroll
    for (int i = 0; i < 16; i++) {
        v[i] = expf(v[i] - M);
        s += v[i];
    }
    __syncthreads();
    #pragma unroll
    for (int o = 16; o > 0; o >>= 1)
        s += __shfl_xor_sync(0xffffffffu, s, o);
    if ((tid & 31) == 0) red[tid >> 5] = s;
    __syncthreads();
    float tot = 0.f;
    #pragma unroll
    for (int i = 0; i < 8; i++) tot += red[i];
    const float inv = 1.0f / tot;

    __half* ph = oh + (size_t)row * n;
    float d = 0.f;
    #pragma unroll
    for (int i = 0; i < 16; i++) {
        int j = tid + (i << 8);
        float w = v[i] * inv;
        ph[j] = hhi(w);
        d += w * bv[j];
    }
    __syncthreads();
    #pragma unroll
    for (int o = 16; o > 0; o >>= 1)
        d += __shfl_xor_sync(0xffffffffu, d, o);
    if ((tid & 31) == 0) red[tid >> 5] = d;
    __syncthreads();
    if (tid == 0) {
        float td = 0.f;
        #pragma unroll
        for (int i = 0; i < 8; i++) td += red[i];
        avb[row] = td;
    }
}

// ---------------- host ------------------------------------------------------
extern "C" void kernel_launch(void* const* d_in, const int* in_sizes, int n_in,
                              void* d_out, int out_size)
{
    (void)in_sizes; (void)n_in; (void)out_size;
    const float* tokens = (const float*)d_in[0];
    const float* Wq = (const float*)d_in[1];
    const float* bq = (const float*)d_in[2];
    const float* Wk = (const float*)d_in[3];
    const float* bk = (const float*)d_in[4];
    const float* Wv = (const float*)d_in[5];
    const float* bv = (const float*)d_in[6];
    const float* Wp = (const float*)d_in[7];
    const float* bp = (const float*)d_in[8];
    float* out = (float*)d_out;

    __half *X, *wtH, *wtL, *wkH, *wkL, *wvH, *wpH, *ttH, *ttL;
    __half *A2H, *A2L, *GH, *GL, *PT, *attH;
    float *S, *part, *u, *alpha, *betat, *avb, *wpc;
    cudaGetSymbolAddress((void**)&X, g_X);
    cudaGetSymbolAddress((void**)&wtH, g_wtH);
    cudaGetSymbolAddress((void**)&wtL, g_wtL);
    cudaGetSymbolAddress((void**)&wkH, g_wkH);
    cudaGetSymbolAddress((void**)&wkL, g_wkL);
    cudaGetSymbolAddress((void**)&wvH, g_wvH);
    cudaGetSymbolAddress((void**)&wpH, g_wpH);
    cudaGetSymbolAddress((void**)&ttH, g_ttH);
    cudaGetSymbolAddress((void**)&ttL, g_ttL);
    cudaGetSymbolAddress((void**)&A2H, g_A2H);
    cudaGetSymbolAddress((void**)&A2L, g_A2L);
    cudaGetSymbolAddress((void**)&GH, g_GH);
    cudaGetSymbolAddress((void**)&GL, g_GL);
    cudaGetSymbolAddress((void**)&PT, g_PT);
    cudaGetSymbolAddress((void**)&attH, g_attH);
    cudaGetSymbolAddress((void**)&S, g_S);
    cudaGetSymbolAddress((void**)&part, g_part);
    cudaGetSymbolAddress((void**)&u, g_u);
    cudaGetSymbolAddress((void**)&alpha, g_alpha);
    cudaGetSymbolAddress((void**)&betat, g_betat);
    cudaGetSymbolAddress((void**)&avb, g_avb);
    cudaGetSymbolAddress((void**)&wpc, g_wpc);

    const int T = TT, E = EE;
    const int HM = E / 2;                     // row-half of the post-G chain
    const size_t offE = (size_t)HM * E;       // element offset into [E,E] mats
    const size_t offT = (size_t)HM * T;       // element offset into [E,T] out

    static bool init_done = false;
    static cudaStream_t sB = nullptr;
    static cudaEvent_t eF = nullptr, eT = nullptr, eP = nullptr;
    static cudaEvent_t eJ = nullptr, eG = nullptr, eEnd = nullptr;
    if (!init_done) {
        cudaFuncSetAttribute(gemm_mma<1, 1>, cudaFuncAttributeMaxDynamicSharedMemorySize, NST * STAGE);
        cudaFuncSetAttribute(gemm_mma<1, 0>, cudaFuncAttributeMaxDynamicSharedMemorySize, NST * STAGE);
        cudaFuncSetAttribute(gemm_mma<0, 0>, cudaFuncAttributeMaxDynamicSharedMemorySize, NST * STAGE);
        cudaFuncSetAttribute(gemm_s<2, 0>, cudaFuncAttributeMaxDynamicSharedMemorySize, S_NST * S_STAGE);
        cudaFuncSetAttribute(gemm_s<0, 3>, cudaFuncAttributeMaxDynamicSharedMemorySize, S_NST * S_STAGE);
        cudaStreamCreateWithFlags(&sB, cudaStreamNonBlocking);
        cudaEventCreateWithFlags(&eF, cudaEventDisableTiming);
        cudaEventCreateWithFlags(&eT, cudaEventDisableTiming);
        cudaEventCreateWithFlags(&eP, cudaEventDisableTiming);
        cudaEventCreateWithFlags(&eJ, cudaEventDisableTiming);
        cudaEventCreateWithFlags(&eG, cudaEventDisableTiming);
        cudaEventCreateWithFlags(&eEnd, cudaEventDisableTiming);
        init_done = true;
    }
    const size_t smem  = NST * STAGE;
    const size_t smemS = S_NST * S_STAGE;
    dim3 blkT(32, 8);

    // fork side stream at the very start
    cudaEventRecord(eF, 0);
    cudaStreamWaitEvent(sB, eF, 0);

    // --- stream 0: tokens^T (split) -> G -> top half pipeline ---
    splitT_kernel<<<dim3(E / 32, T / 32), blkT>>>(tokens, ttH, ttL, T, E);
    cudaEventRecord(eT, 0);

    // --- side stream: all W-preps + colsums + matvecs, then Wp^T + PT ---
    splitT_kernel<<<dim3(E / 32, E / 32), blkT, 0, sB>>>(Wq, wtH, wtL, E, E);
    splitT_kernel<<<dim3(E / 32, E / 32), blkT, 0, sB>>>(Wk, wkH, wkL, E, E);
    split_kernel<<<(unsigned)((size_t)E * E / 4 / 256), 256, 0, sB>>>(
        Wv, wvH, nullptr, (size_t)E * E / 4);
    colsum_partial<<<dim3(E / 256, 32), 256, 0, sB>>>(tokens, part, E);
    colsum_final<<<E / 256, 256, 0, sB>>>(part, u, E, 32);
    matvecT<<<E / 256, 256, 0, sB>>>(Wq, u, bq, 0.f, alpha);
    matvecT<<<E / 256, 256, 0, sB>>>(Wk, u, bk, (float)T, betat);
    colsum_partial<<<dim3(T / 256, 32), 256, 0, sB>>>(Wp, part, T);
    colsum_final<<<T / 256, 256, 0, sB>>>(part, wpc, T, 32);
    cudaEventRecord(eP, sB);            // small preps done
    splitT_kernel<<<dim3(T / 32, T / 32), blkT, 0, sB>>>(Wp, wpH, nullptr, T, T);
    cudaStreamWaitEvent(sB, eT, 0);     // PT needs tokens^T
    gemm_s<2, 0><<<dim3(E / BN, T / BM), 512, smemS, sB>>>(
        wpH, ttH, PT, nullptr, nullptr, nullptr, T, E, T);
    cudaEventRecord(eJ, sB);            // PT ready

    // G = tok^T tok [E,E], symmetric, split out  (stream 0)
    gemm_mma<1, 1><<<dim3(E / BN, E / BM), 256, smem>>>(
        ttH, ttL, ttH, ttL, GH, GL, E, E, T);
    cudaEventRecord(eG, 0);

    cudaStreamWaitEvent(0, eP, 0);      // top pipeline needs W-preps

    // ===== TOP half pipeline (rows [0, HM)) on stream 0 =====
    gemm_mma<1, 0><<<dim3(E / BN, HM / BM), 256, smem>>>(
        wtH, wtL, GH, GL, A2H, A2L, HM, E, E);
    gemm_mma<0, 0><<<dim3(E / BN, HM / BM), 256, smem>>>(
        A2H, A2L, wkH, wkL, S, nullptr, HM, E, E);
    softmax_half<<<HM, 256>>>(S, attH, E, bq, bk, alpha, betat, bv, avb);
    gemm_s<2, 0><<<dim3(E / BN, HM / BM), 512, smemS>>>(
        attH, wvH, X, nullptr, nullptr, nullptr, HM, E, E);
    cudaStreamWaitEvent(0, eJ, 0);      // final needs PT
    gemm_s<0, 3><<<dim3(T / BN, HM / BM), 512, smemS>>>(
        X, PT, out, bp, avb, wpc, HM, T, E);

    // ===== BOTTOM half pipeline (rows [HM, E)) on side stream =====
    cudaStreamWaitEvent(sB, eG, 0);     // needs G (eP already ordered on sB)
    gemm_mma<1, 0><<<dim3(E / BN, HM / BM), 256, smem, sB>>>(
        wtH + offE, wtL + offE, GH, GL, A2H + offE, A2L + offE, HM, E, E);
    gemm_mma<0, 0><<<dim3(E / BN, HM / BM), 256, smem, sB>>>(
        A2H + offE, A2L + offE, wkH, wkL, S + offE, nullptr, HM, E, E);
    softmax_half<<<HM, 256, 0, sB>>>(S + offE, attH + offE, E,
                                     bq + HM, bk, alpha + HM, betat, bv, avb + HM);
    gemm_s<2, 0><<<dim3(E / BN, HM / BM), 512, smemS, sB>>>(
        attH + offE, wvH, X + offE, nullptr, nullptr, nullptr, HM, E, E);
    gemm_s<0, 3><<<dim3(T / BN, HM / BM), 512, smemS, sB>>>(
        X + offE, PT, out + offT, bp, avb + HM, wpc, HM, T, E);
    cudaEventRecord(eEnd, sB);

    // join: harness synchronizes stream 0
    cudaStreamWaitEvent(0, eEnd, 0);
}